// round 1
// baseline (speedup 1.0000x reference)
#include <cuda_runtime.h>
#include <math.h>

#define HW     16384
#define WIMG   128
#define HIMG   128
#define DIM    384
#define BATCH  4
#define NHEAD  8
#define CHAN   48
#define DTOT   786432   /* CHAN*HW : per-head flattened dim */

// ---------------- scratch (static device globals; no allocation) ----------------
__device__ float g_qkv[BATCH * 3 * DIM * HW];  // conv1x1 output  (302 MB)
__device__ float g_dw [BATCH * 3 * DIM * HW];  // dwconv output   (302 MB)
__device__ float g_mix[BATCH * DIM * HW];      // attn@v output   (100 MB)
__device__ float g_sumsq[64];                  // [b][q/k][n] squared norms
__device__ float g_dots[256];                  // [b][n][m] raw dot products
__device__ float g_attn[256];                  // [b][n][m] softmax weights

// ---------------- tiny init ----------------
__global__ void zero_kernel() {
    int t = threadIdx.x;
    if (t < 64)  g_sumsq[t] = 0.f;
    if (t < 256) g_dots[t]  = 0.f;
}

// ---------------- GEMM 1: qkv = W_qkv(1152x384) @ X_b(384x16384) + bias ----------------
// 128x128 block tile, BK=16, 256 threads, 8x8 per-thread microtile.
__global__ __launch_bounds__(256) void gemm_qkv(const float* __restrict__ Wt,
                                                const float* __restrict__ bias,
                                                const float* __restrict__ X) {
    __shared__ float As[16][128];
    __shared__ float Bs[16][128];
    int tid = threadIdx.x;
    int n0  = blockIdx.x * 128;
    int b   = n0 >> 14;              // 16384 cols per batch
    int p0  = n0 & (HW - 1);
    int m0  = blockIdx.y * 128;
    const float* Bp = X + (size_t)b * DIM * HW + p0;   // B[k][n] = Bp[k*HW + n]
    const float* Ap = Wt + (size_t)m0 * DIM;           // A[m][k] = Ap[m*DIM + k]

    float acc[8][8];
#pragma unroll
    for (int i = 0; i < 8; i++)
#pragma unroll
        for (int j = 0; j < 8; j++) acc[i][j] = 0.f;

    int ty = tid >> 4, tx = tid & 15;

    for (int k0 = 0; k0 < DIM; k0 += 16) {
#pragma unroll
        for (int l = 0; l < 2; l++) {                   // A tile: 128x16
            int idx = tid + l * 256;
            int row = idx >> 2, k4 = (idx & 3) * 4;
            float4 av = *(const float4*)(Ap + (size_t)row * DIM + k0 + k4);
            As[k4 + 0][row] = av.x; As[k4 + 1][row] = av.y;
            As[k4 + 2][row] = av.z; As[k4 + 3][row] = av.w;
        }
#pragma unroll
        for (int l = 0; l < 2; l++) {                   // B tile: 16x128
            int idx = tid + l * 256;
            int kr = idx >> 5, n4 = (idx & 31) * 4;
            *(float4*)&Bs[kr][n4] = *(const float4*)(Bp + (size_t)(k0 + kr) * HW + n4);
        }
        __syncthreads();
#pragma unroll
        for (int kk = 0; kk < 16; kk++) {
            float a[8], bb[8];
            *(float4*)&a[0]  = *(const float4*)&As[kk][ty * 8];
            *(float4*)&a[4]  = *(const float4*)&As[kk][ty * 8 + 4];
            *(float4*)&bb[0] = *(const float4*)&Bs[kk][tx * 8];
            *(float4*)&bb[4] = *(const float4*)&Bs[kk][tx * 8 + 4];
#pragma unroll
            for (int i = 0; i < 8; i++)
#pragma unroll
                for (int j = 0; j < 8; j++)
                    acc[i][j] = fmaf(a[i], bb[j], acc[i][j]);
        }
        __syncthreads();
    }

    float* outb = g_qkv + (size_t)b * 3 * DIM * HW;
#pragma unroll
    for (int i = 0; i < 8; i++) {
        int row = m0 + ty * 8 + i;
        float bv = bias[row];
        float* orow = outb + (size_t)row * HW + p0 + tx * 8;
        float4 v0 = {acc[i][0] + bv, acc[i][1] + bv, acc[i][2] + bv, acc[i][3] + bv};
        float4 v1 = {acc[i][4] + bv, acc[i][5] + bv, acc[i][6] + bv, acc[i][7] + bv};
        *(float4*)orow       = v0;
        *(float4*)(orow + 4) = v1;
    }
}

// ---------------- dwconv 3x3 (pad 1) + fused q/k sum-of-squares ----------------
__global__ void dwconv_kernel(const float* __restrict__ wdw,
                              const float* __restrict__ bdw) {
    __shared__ float sm[8];
    int bc = blockIdx.z;                 // b*1152 + ch
    int ch = bc % 1152;
    int b  = bc / 1152;
    int x  = blockIdx.x * 32 + threadIdx.x;
    int y  = blockIdx.y * 8  + threadIdx.y;
    const float* in = g_qkv + (size_t)bc * HW;

    float w[9];
#pragma unroll
    for (int i = 0; i < 9; i++) w[i] = wdw[ch * 9 + i];

    float s = bdw[ch];
#pragma unroll
    for (int dy = 0; dy < 3; dy++) {
        int yy = y + dy - 1;
        if (yy < 0 || yy >= HIMG) continue;
#pragma unroll
        for (int dx = 0; dx < 3; dx++) {
            int xx = x + dx - 1;
            if (xx < 0 || xx >= WIMG) continue;
            s = fmaf(w[dy * 3 + dx], in[yy * WIMG + xx], s);
        }
    }
    g_dw[(size_t)bc * HW + y * WIMG + x] = s;

    if (ch < 2 * DIM) {                  // q or k part: accumulate ||.||^2
        float v = s * s;
#pragma unroll
        for (int o = 16; o > 0; o >>= 1) v += __shfl_down_sync(0xffffffffu, v, o);
        if (threadIdx.x == 0) sm[threadIdx.y] = v;
        __syncthreads();
        if (threadIdx.x == 0 && threadIdx.y == 0) {
            float t = 0.f;
#pragma unroll
            for (int i = 0; i < 8; i++) t += sm[i];
            atomicAdd(&g_sumsq[b * 16 + (ch / DIM) * 8 + (ch % DIM) / CHAN], t);
        }
    }
}

// ---------------- dots: dots[b][n][m] = q_n . k_m (unnormalized) ----------------
__global__ __launch_bounds__(256) void dots_kernel() {
    int b = blockIdx.y;
    const float* qb = g_dw + (size_t)b * 3 * DIM * HW;
    const float* kb = qb + (size_t)DIM * HW;
    float acc[64];
#pragma unroll
    for (int j = 0; j < 64; j++) acc[j] = 0.f;

    int tid = threadIdx.x;
    float qv[8], kv[8];
    for (int idx = blockIdx.x * 256 + tid; idx < DTOT; idx += gridDim.x * 256) {
#pragma unroll
        for (int n = 0; n < 8; n++) {
            qv[n] = qb[(size_t)n * DTOT + idx];
            kv[n] = kb[(size_t)n * DTOT + idx];
        }
#pragma unroll
        for (int n = 0; n < 8; n++)
#pragma unroll
            for (int m = 0; m < 8; m++)
                acc[n * 8 + m] = fmaf(qv[n], kv[m], acc[n * 8 + m]);
    }

    __shared__ float red[64];
    if (tid < 64) red[tid] = 0.f;
    __syncthreads();
    int lane = tid & 31;
#pragma unroll
    for (int j = 0; j < 64; j++) {
        float v = acc[j];
#pragma unroll
        for (int o = 16; o > 0; o >>= 1) v += __shfl_down_sync(0xffffffffu, v, o);
        if (lane == 0) atomicAdd(&red[j], v);
    }
    __syncthreads();
    if (tid < 64) atomicAdd(&g_dots[b * 64 + tid], red[tid]);
}

// ---------------- softmax over normalized scores (tiny) ----------------
__global__ void softmax_kernel(const float* __restrict__ temp) {
    int t = threadIdx.x;
    if (t >= 32) return;
    int b = t >> 3, n = t & 7;
    float T  = temp[0];
    float nq = fmaxf(sqrtf(g_sumsq[b * 16 + n]), 1e-12f);
    float s[8], mx = -1e30f;
#pragma unroll
    for (int m = 0; m < 8; m++) {
        float nk = fmaxf(sqrtf(g_sumsq[b * 16 + 8 + m]), 1e-12f);
        s[m] = g_dots[b * 64 + n * 8 + m] / (nq * nk) * T;
        mx = fmaxf(mx, s[m]);
    }
    float sum = 0.f;
#pragma unroll
    for (int m = 0; m < 8; m++) { s[m] = expf(s[m] - mx); sum += s[m]; }
    float inv = 1.f / sum;
#pragma unroll
    for (int m = 0; m < 8; m++) g_attn[b * 64 + n * 8 + m] = s[m] * inv;
}

// ---------------- mix: out[b][n][d] = sum_m attn[b][n][m] * v[b][m][d] ----------------
__global__ __launch_bounds__(256) void mix_kernel() {
    int b = blockIdx.y;
    __shared__ float at[64];
    if (threadIdx.x < 64) at[threadIdx.x] = g_attn[b * 64 + threadIdx.x];
    __syncthreads();
    const float* vb = g_dw + ((size_t)b * 3 * DIM + 2 * DIM) * HW;
    float* ob = g_mix + (size_t)b * DIM * HW;
    for (int idx = blockIdx.x * blockDim.x + threadIdx.x; idx < DTOT;
         idx += gridDim.x * blockDim.x) {
        float v[8];
#pragma unroll
        for (int m = 0; m < 8; m++) v[m] = vb[(size_t)m * DTOT + idx];
#pragma unroll
        for (int n = 0; n < 8; n++) {
            float s = 0.f;
#pragma unroll
            for (int m = 0; m < 8; m++) s = fmaf(at[n * 8 + m], v[m], s);
            ob[(size_t)n * DTOT + idx] = s;
        }
    }
}

// ---------------- GEMM 2: out = W_proj(384x384) @ mix + bias + residual ----------------
__global__ __launch_bounds__(256) void gemm_proj(const float* __restrict__ Wt,
                                                 const float* __restrict__ bias,
                                                 const float* __restrict__ Xres,
                                                 float* __restrict__ out) {
    __shared__ float As[16][128];
    __shared__ float Bs[16][128];
    int tid = threadIdx.x;
    int n0  = blockIdx.x * 128;
    int b   = n0 >> 14;
    int p0  = n0 & (HW - 1);
    int m0  = blockIdx.y * 128;
    const float* Bp = g_mix + (size_t)b * DIM * HW + p0;
    const float* Ap = Wt + (size_t)m0 * DIM;

    float acc[8][8];
#pragma unroll
    for (int i = 0; i < 8; i++)
#pragma unroll
        for (int j = 0; j < 8; j++) acc[i][j] = 0.f;

    int ty = tid >> 4, tx = tid & 15;

    for (int k0 = 0; k0 < DIM; k0 += 16) {
#pragma unroll
        for (int l = 0; l < 2; l++) {
            int idx = tid + l * 256;
            int row = idx >> 2, k4 = (idx & 3) * 4;
            float4 av = *(const float4*)(Ap + (size_t)row * DIM + k0 + k4);
            As[k4 + 0][row] = av.x; As[k4 + 1][row] = av.y;
            As[k4 + 2][row] = av.z; As[k4 + 3][row] = av.w;
        }
#pragma unroll
        for (int l = 0; l < 2; l++) {
            int idx = tid + l * 256;
            int kr = idx >> 5, n4 = (idx & 31) * 4;
            *(float4*)&Bs[kr][n4] = *(const float4*)(Bp + (size_t)(k0 + kr) * HW + n4);
        }
        __syncthreads();
#pragma unroll
        for (int kk = 0; kk < 16; kk++) {
            float a[8], bb[8];
            *(float4*)&a[0]  = *(const float4*)&As[kk][ty * 8];
            *(float4*)&a[4]  = *(const float4*)&As[kk][ty * 8 + 4];
            *(float4*)&bb[0] = *(const float4*)&Bs[kk][tx * 8];
            *(float4*)&bb[4] = *(const float4*)&Bs[kk][tx * 8 + 4];
#pragma unroll
            for (int i = 0; i < 8; i++)
#pragma unroll
                for (int j = 0; j < 8; j++)
                    acc[i][j] = fmaf(a[i], bb[j], acc[i][j]);
        }
        __syncthreads();
    }

#pragma unroll
    for (int i = 0; i < 8; i++) {
        int row = m0 + ty * 8 + i;
        float bv = bias[row];
        size_t off = ((size_t)b * DIM + row) * HW + p0 + tx * 8;
        float4 r0 = *(const float4*)(Xres + off);
        float4 r1 = *(const float4*)(Xres + off + 4);
        float4 v0 = {acc[i][0] + bv + r0.x, acc[i][1] + bv + r0.y,
                     acc[i][2] + bv + r0.z, acc[i][3] + bv + r0.w};
        float4 v1 = {acc[i][4] + bv + r1.x, acc[i][5] + bv + r1.y,
                     acc[i][6] + bv + r1.z, acc[i][7] + bv + r1.w};
        *(float4*)(out + off)     = v0;
        *(float4*)(out + off + 4) = v1;
    }
}

// ---------------- launch ----------------
extern "C" void kernel_launch(void* const* d_in, const int* in_sizes, int n_in,
                              void* d_out, int out_size) {
    const float* x           = (const float*)d_in[0];
    const float* temperature = (const float*)d_in[1];
    const float* w_qkv       = (const float*)d_in[2];
    const float* b_qkv       = (const float*)d_in[3];
    const float* w_dw        = (const float*)d_in[4];
    const float* b_dw        = (const float*)d_in[5];
    const float* w_proj      = (const float*)d_in[6];
    const float* b_proj      = (const float*)d_in[7];
    float* out = (float*)d_out;

    zero_kernel<<<1, 256>>>();
    gemm_qkv<<<dim3(512, 9), 256>>>(w_qkv, b_qkv, x);
    dwconv_kernel<<<dim3(WIMG / 32, HIMG / 8, BATCH * 3 * DIM), dim3(32, 8)>>>(w_dw, b_dw);
    dots_kernel<<<dim3(256, BATCH), 256>>>();
    softmax_kernel<<<1, 32>>>(temperature);
    mix_kernel<<<dim3(192, BATCH), 256>>>();
    gemm_proj<<<dim3(512, 3), 256>>>(w_proj, b_proj, x, out);
}

// round 6
// speedup vs baseline: 4.2261x; 4.2261x over previous
#include <cuda_runtime.h>
#include <cuda_bf16.h>
#include <cstdint>
#include <math.h>

#define HW    16384
#define WIMG  128
#define HIMG  128
#define DIM   384
#define BATCH 4
#define HL    393216   /* per-head bf162 count: 48*16384/2 */

/* ---------------- scratch (static device globals) ---------------- */
__device__ __align__(16) __nv_bfloat16 g_xbf [BATCH * DIM * HW];
__device__ __align__(16) __nv_bfloat16 g_qkv [BATCH * 3 * DIM * HW];
__device__ __align__(16) __nv_bfloat16 g_dw  [BATCH * 3 * DIM * HW];
__device__ __align__(16) __nv_bfloat16 g_mix [BATCH * DIM * HW];
__device__ __align__(16) __nv_bfloat16 g_wqkv[3 * DIM * DIM];
__device__ __align__(16) __nv_bfloat16 g_wpro[DIM * DIM];
__device__ float g_sumsq[64];
__device__ float g_dots[256];
__device__ float g_attn[256];

/* ---------------- PTX macros (unsigned int operands only) ---------------- */
#define CP_ASYNC16(saddr, gaddr) \
    asm volatile("cp.async.cg.shared.global [%0], [%1], 16;\n" :: "r"(saddr), "l"(gaddr))
#define CP_COMMIT() asm volatile("cp.async.commit_group;\n" ::: "memory")
#define CP_WAIT1()  asm volatile("cp.async.wait_group 1;\n" ::: "memory")
#define LDSM_X4(r0, r1, r2, r3, addr) \
    asm volatile("ldmatrix.sync.aligned.m8n8.x4.shared.b16 {%0,%1,%2,%3}, [%4];\n" \
                 : "=r"(r0), "=r"(r1), "=r"(r2), "=r"(r3) : "r"(addr))
#define LDSM_X2T(r0, r1, addr) \
    asm volatile("ldmatrix.sync.aligned.m8n8.x2.trans.shared.b16 {%0,%1}, [%2];\n" \
                 : "=r"(r0), "=r"(r1) : "r"(addr))
#define MMA16816(c0, c1, c2, c3, a0, a1, a2, a3, b0, b1) \
    asm volatile("mma.sync.aligned.m16n8k16.row.col.f32.bf16.bf16.f32 " \
                 "{%0,%1,%2,%3}, {%4,%5,%6,%7}, {%8,%9}, {%0,%1,%2,%3};\n" \
                 : "+f"(c0), "+f"(c1), "+f"(c2), "+f"(c3) \
                 : "r"(a0), "r"(a1), "r"(a2), "r"(a3), "r"(b0), "r"(b1))

/* ---------------- tiny init ---------------- */
__global__ void zero_kernel() {
    int t = threadIdx.x;
    if (t < 64)  g_sumsq[t] = 0.f;
    if (t < 256) g_dots[t]  = 0.f;
}

/* ---------------- conversions fp32 -> bf16 ---------------- */
__global__ __launch_bounds__(256) void convert_x(const float* __restrict__ x) {
    int i = blockIdx.x * 256 + threadIdx.x;
    float4 v = ((const float4*)x)[i];
    __nv_bfloat162* o = (__nv_bfloat162*)g_xbf;
    o[2 * i]     = __floats2bfloat162_rn(v.x, v.y);
    o[2 * i + 1] = __floats2bfloat162_rn(v.z, v.w);
}

__global__ __launch_bounds__(256) void convert_w(const float* __restrict__ wq,
                                                 const float* __restrict__ wp) {
    int i = blockIdx.x * 256 + threadIdx.x;
    if (i < 3 * DIM * DIM) {
        g_wqkv[i] = __float2bfloat16(wq[i]);
    } else {
        g_wpro[i - 3 * DIM * DIM] = __float2bfloat16(wp[i - 3 * DIM * DIM]);
    }
}

/* ---------------- GEMM 1: qkv = Wqkv(1152x384) @ Xb(384x16384), bf16 HMMA -------- */
__global__ __launch_bounds__(256) void gemm_qkv_tc(const float* __restrict__ bias) {
    __shared__ __nv_bfloat16 As[2][128][40];
    __shared__ __nv_bfloat16 Bs[2][32][136];

    int tid = threadIdx.x;
    int bb  = blockIdx.x >> 7;
    int n0  = (blockIdx.x & 127) << 7;
    int m0  = blockIdx.y << 7;
    const __nv_bfloat16* Ap = g_wqkv + (size_t)m0 * DIM;
    const __nv_bfloat16* Bp = g_xbf + (size_t)bb * DIM * HW + n0;

    unsigned int asBase = (unsigned int)__cvta_generic_to_shared(&As[0][0][0]);
    unsigned int bsBase = (unsigned int)__cvta_generic_to_shared(&Bs[0][0][0]);

    int arow = tid >> 2, acol = (tid & 3) * 8;
    int brow = tid >> 4, bcol = (tid & 15) * 8;
    int wrp = tid >> 5, ln = tid & 31;
    int wm = wrp >> 2, wn = wrp & 3;

    float acc[4][4][4];
#pragma unroll
    for (int i = 0; i < 4; i++) {
#pragma unroll
        for (int j = 0; j < 4; j++) {
#pragma unroll
            for (int r = 0; r < 4; r++) { acc[i][j][r] = 0.f; }
        }
    }

    /* prologue: stage 0, k0 = 0 */
    {
        const __nv_bfloat16* ap0 = Ap + (size_t)arow * DIM + acol;
        unsigned int sa0 = asBase + (unsigned int)((arow * 40 + acol) * 2);
        unsigned int sa1 = asBase + (unsigned int)(((arow + 64) * 40 + acol) * 2);
        CP_ASYNC16(sa0, ap0);
        CP_ASYNC16(sa1, ap0 + 64 * DIM);
        const __nv_bfloat16* bp0 = Bp + (size_t)brow * HW + bcol;
        unsigned int sb0 = bsBase + (unsigned int)((brow * 136 + bcol) * 2);
        unsigned int sb1 = bsBase + (unsigned int)(((brow + 16) * 136 + bcol) * 2);
        CP_ASYNC16(sb0, bp0);
        CP_ASYNC16(sb1, bp0 + 16 * HW);
    }
    CP_COMMIT();

    for (int kt = 0; kt < 12; kt++) {
        if (kt < 11) {
            int sn = (kt + 1) & 1;
            int k0 = (kt + 1) * 32;
            const __nv_bfloat16* ap1 = Ap + (size_t)arow * DIM + k0 + acol;
            unsigned int sa0 = asBase + (unsigned int)(((sn * 128 + arow) * 40 + acol) * 2);
            unsigned int sa1 = asBase + (unsigned int)(((sn * 128 + arow + 64) * 40 + acol) * 2);
            CP_ASYNC16(sa0, ap1);
            CP_ASYNC16(sa1, ap1 + 64 * DIM);
            const __nv_bfloat16* bp1 = Bp + (size_t)(k0 + brow) * HW + bcol;
            unsigned int sb0 = bsBase + (unsigned int)(((sn * 32 + brow) * 136 + bcol) * 2);
            unsigned int sb1 = bsBase + (unsigned int)(((sn * 32 + brow + 16) * 136 + bcol) * 2);
            CP_ASYNC16(sb0, bp1);
            CP_ASYNC16(sb1, bp1 + 16 * HW);
        }
        CP_COMMIT();
        CP_WAIT1();
        __syncthreads();
        int st = kt & 1;
#pragma unroll
        for (int ks = 0; ks < 2; ks++) {
            unsigned int af[4][4];
            unsigned int bfr[4][2];
#pragma unroll
            for (int mi = 0; mi < 4; mi++) {
                unsigned int aaddr = asBase + (unsigned int)(
                    ((st * 128 + wm * 64 + mi * 16 + (ln & 15)) * 40 +
                     ks * 16 + ((ln >> 4) << 3)) * 2);
                LDSM_X4(af[mi][0], af[mi][1], af[mi][2], af[mi][3], aaddr);
            }
#pragma unroll
            for (int ni = 0; ni < 4; ni++) {
                unsigned int baddr = bsBase + (unsigned int)(
                    ((st * 32 + ks * 16 + (ln & 15)) * 136 + wn * 32 + ni * 8) * 2);
                LDSM_X2T(bfr[ni][0], bfr[ni][1], baddr);
            }
#pragma unroll
            for (int mi = 0; mi < 4; mi++) {
#pragma unroll
                for (int ni = 0; ni < 4; ni++) {
                    MMA16816(acc[mi][ni][0], acc[mi][ni][1], acc[mi][ni][2], acc[mi][ni][3],
                             af[mi][0], af[mi][1], af[mi][2], af[mi][3],
                             bfr[ni][0], bfr[ni][1]);
                }
            }
        }
        __syncthreads();
    }

    /* epilogue: +bias, bf16 out */
    int rbase = m0 + wm * 64;
    int cbase = n0 + wn * 32 + (ln & 3) * 2;
#pragma unroll
    for (int mi = 0; mi < 4; mi++) {
        int r0 = rbase + mi * 16 + (ln >> 2);
        float bv0 = bias[r0];
        float bv1 = bias[r0 + 8];
#pragma unroll
        for (int ni = 0; ni < 4; ni++) {
            int c = cbase + ni * 8;
            __nv_bfloat162* d0 = (__nv_bfloat162*)&g_qkv[((size_t)bb * 1152 + r0) * HW + c];
            __nv_bfloat162* d1 = (__nv_bfloat162*)&g_qkv[((size_t)bb * 1152 + r0 + 8) * HW + c];
            *d0 = __floats2bfloat162_rn(acc[mi][ni][0] + bv0, acc[mi][ni][1] + bv0);
            *d1 = __floats2bfloat162_rn(acc[mi][ni][2] + bv1, acc[mi][ni][3] + bv1);
        }
    }
}

/* ---------------- GEMM 2: out = Wproj(384x384) @ mix + bias + residual (fp32) ----- */
__global__ __launch_bounds__(256) void gemm_proj_tc(const float* __restrict__ bias,
                                                    const float* __restrict__ resid,
                                                    float* __restrict__ outf) {
    __shared__ __nv_bfloat16 As[2][128][40];
    __shared__ __nv_bfloat16 Bs[2][32][136];

    int tid = threadIdx.x;
    int bb  = blockIdx.x >> 7;
    int n0  = (blockIdx.x & 127) << 7;
    int m0  = blockIdx.y << 7;
    const __nv_bfloat16* Ap = g_wpro + (size_t)m0 * DIM;
    const __nv_bfloat16* Bp = g_mix + (size_t)bb * DIM * HW + n0;

    unsigned int asBase = (unsigned int)__cvta_generic_to_shared(&As[0][0][0]);
    unsigned int bsBase = (unsigned int)__cvta_generic_to_shared(&Bs[0][0][0]);

    int arow = tid >> 2, acol = (tid & 3) * 8;
    int brow = tid >> 4, bcol = (tid & 15) * 8;
    int wrp = tid >> 5, ln = tid & 31;
    int wm = wrp >> 2, wn = wrp & 3;

    float acc[4][4][4];
#pragma unroll
    for (int i = 0; i < 4; i++) {
#pragma unroll
        for (int j = 0; j < 4; j++) {
#pragma unroll
            for (int r = 0; r < 4; r++) { acc[i][j][r] = 0.f; }
        }
    }

    {
        const __nv_bfloat16* ap0 = Ap + (size_t)arow * DIM + acol;
        unsigned int sa0 = asBase + (unsigned int)((arow * 40 + acol) * 2);
        unsigned int sa1 = asBase + (unsigned int)(((arow + 64) * 40 + acol) * 2);
        CP_ASYNC16(sa0, ap0);
        CP_ASYNC16(sa1, ap0 + 64 * DIM);
        const __nv_bfloat16* bp0 = Bp + (size_t)brow * HW + bcol;
        unsigned int sb0 = bsBase + (unsigned int)((brow * 136 + bcol) * 2);
        unsigned int sb1 = bsBase + (unsigned int)(((brow + 16) * 136 + bcol) * 2);
        CP_ASYNC16(sb0, bp0);
        CP_ASYNC16(sb1, bp0 + 16 * HW);
    }
    CP_COMMIT();

    for (int kt = 0; kt < 12; kt++) {
        if (kt < 11) {
            int sn = (kt + 1) & 1;
            int k0 = (kt + 1) * 32;
            const __nv_bfloat16* ap1 = Ap + (size_t)arow * DIM + k0 + acol;
            unsigned int sa0 = asBase + (unsigned int)(((sn * 128 + arow) * 40 + acol) * 2);
            unsigned int sa1 = asBase + (unsigned int)(((sn * 128 + arow + 64) * 40 + acol) * 2);
            CP_ASYNC16(sa0, ap1);
            CP_ASYNC16(sa1, ap1 + 64 * DIM);
            const __nv_bfloat16* bp1 = Bp + (size_t)(k0 + brow) * HW + bcol;
            unsigned int sb0 = bsBase + (unsigned int)(((sn * 32 + brow) * 136 + bcol) * 2);
            unsigned int sb1 = bsBase + (unsigned int)(((sn * 32 + brow + 16) * 136 + bcol) * 2);
            CP_ASYNC16(sb0, bp1);
            CP_ASYNC16(sb1, bp1 + 16 * HW);
        }
        CP_COMMIT();
        CP_WAIT1();
        __syncthreads();
        int st = kt & 1;
#pragma unroll
        for (int ks = 0; ks < 2; ks++) {
            unsigned int af[4][4];
            unsigned int bfr[4][2];
#pragma unroll
            for (int mi = 0; mi < 4; mi++) {
                unsigned int aaddr = asBase + (unsigned int)(
                    ((st * 128 + wm * 64 + mi * 16 + (ln & 15)) * 40 +
                     ks * 16 + ((ln >> 4) << 3)) * 2);
                LDSM_X4(af[mi][0], af[mi][1], af[mi][2], af[mi][3], aaddr);
            }
#pragma unroll
            for (int ni = 0; ni < 4; ni++) {
                unsigned int baddr = bsBase + (unsigned int)(
                    ((st * 32 + ks * 16 + (ln & 15)) * 136 + wn * 32 + ni * 8) * 2);
                LDSM_X2T(bfr[ni][0], bfr[ni][1], baddr);
            }
#pragma unroll
            for (int mi = 0; mi < 4; mi++) {
#pragma unroll
                for (int ni = 0; ni < 4; ni++) {
                    MMA16816(acc[mi][ni][0], acc[mi][ni][1], acc[mi][ni][2], acc[mi][ni][3],
                             af[mi][0], af[mi][1], af[mi][2], af[mi][3],
                             bfr[ni][0], bfr[ni][1]);
                }
            }
        }
        __syncthreads();
    }

    int rbase = m0 + wm * 64;
    int cbase = n0 + wn * 32 + (ln & 3) * 2;
#pragma unroll
    for (int mi = 0; mi < 4; mi++) {
        int r0 = rbase + mi * 16 + (ln >> 2);
        float bv0 = bias[r0];
        float bv1 = bias[r0 + 8];
#pragma unroll
        for (int ni = 0; ni < 4; ni++) {
            int c = cbase + ni * 8;
            size_t o0 = ((size_t)bb * DIM + r0) * HW + c;
            size_t o1 = ((size_t)bb * DIM + r0 + 8) * HW + c;
            float2 x0 = *(const float2*)(resid + o0);
            float2 x1 = *(const float2*)(resid + o1);
            float2 v0, v1;
            v0.x = acc[mi][ni][0] + bv0 + x0.x;
            v0.y = acc[mi][ni][1] + bv0 + x0.y;
            v1.x = acc[mi][ni][2] + bv1 + x1.x;
            v1.y = acc[mi][ni][3] + bv1 + x1.y;
            *(float2*)(outf + o0) = v0;
            *(float2*)(outf + o1) = v1;
        }
    }
}

/* ---------------- dwconv 3x3 (pad 1), bf16 in/out, fused q/k sumsq ---------------- */
__global__ __launch_bounds__(256) void dwconv_kernel(const float* __restrict__ wdw,
                                                     const float* __restrict__ bdw) {
    int bc = blockIdx.z;
    int ch = bc % (3 * DIM);
    int bi = bc / (3 * DIM);
    int tid = threadIdx.x;
    int tx = tid & 15, ty = tid >> 4;
    int x0 = tx * 8;
    int yy0 = blockIdx.y * 16 + ty;
    const __nv_bfloat16* inp = g_qkv + (size_t)bc * HW;

    float w[9];
#pragma unroll
    for (int i = 0; i < 9; i++) { w[i] = wdw[ch * 9 + i]; }

    float bv = bdw[ch];
    float acc[8];
#pragma unroll
    for (int j = 0; j < 8; j++) { acc[j] = bv; }

#pragma unroll
    for (int dy = 0; dy < 3; dy++) {
        int yy = yy0 + dy - 1;
        if (yy < 0 || yy >= HIMG) continue;
        const __nv_bfloat16* rp = inp + yy * WIMG + x0;
        float4 raw = *(const float4*)rp;
        const __nv_bfloat162* pr = (const __nv_bfloat162*)&raw;
        float m[8];
#pragma unroll
        for (int i = 0; i < 4; i++) {
            float2 t = __bfloat1622float2(pr[i]);
            m[2 * i] = t.x;
            m[2 * i + 1] = t.y;
        }
        float lft = (x0 > 0)        ? __bfloat162float(rp[-1]) : 0.f;
        float rgt = (x0 + 8 < WIMG) ? __bfloat162float(rp[8])  : 0.f;
        float w0 = w[dy * 3], w1 = w[dy * 3 + 1], w2 = w[dy * 3 + 2];
#pragma unroll
        for (int j = 0; j < 8; j++) {
            float lv = (j > 0) ? m[j - 1] : lft;
            float rv = (j < 7) ? m[j + 1] : rgt;
            acc[j] = fmaf(w0, lv, fmaf(w1, m[j], fmaf(w2, rv, acc[j])));
        }
    }

    float4 packed;
    __nv_bfloat16* ob = (__nv_bfloat16*)&packed;
    float ss = 0.f;
#pragma unroll
    for (int j = 0; j < 8; j++) {
        ob[j] = __float2bfloat16(acc[j]);
        float t = __bfloat162float(ob[j]);
        ss = fmaf(t, t, ss);
    }
    *(float4*)(g_dw + (size_t)bc * HW + yy0 * WIMG + x0) = packed;

#pragma unroll
    for (int o = 16; o > 0; o >>= 1) { ss += __shfl_down_sync(0xffffffffu, ss, o); }
    __shared__ float smred[8];
    int ln = tid & 31, wrp = tid >> 5;
    if (ln == 0) smred[wrp] = ss;
    __syncthreads();
    if (tid == 0 && ch < 2 * DIM) {
        float t = 0.f;
#pragma unroll
        for (int i = 0; i < 8; i++) { t += smred[i]; }
        atomicAdd(&g_sumsq[bi * 16 + (ch >= DIM ? 8 : 0) + (ch % DIM) / 48], t);
    }
}

/* ---------------- dots: raw q.k Gram (bf16 reads, fp32 accum) ---------------- */
__global__ __launch_bounds__(256) void dots_kernel() {
    int bi = blockIdx.y;
    const __nv_bfloat162* qb = (const __nv_bfloat162*)(g_dw + (size_t)bi * 3 * DIM * HW);
    const __nv_bfloat162* kb = qb + (size_t)DIM * HW / 2;
    float acc[64];
#pragma unroll
    for (int j = 0; j < 64; j++) { acc[j] = 0.f; }

    int tid = threadIdx.x;
    for (int i = blockIdx.x * 256 + tid; i < HL; i += gridDim.x * 256) {
        float2 qv[8], kv[8];
#pragma unroll
        for (int n = 0; n < 8; n++) {
            qv[n] = __bfloat1622float2(qb[(size_t)n * HL + i]);
            kv[n] = __bfloat1622float2(kb[(size_t)n * HL + i]);
        }
#pragma unroll
        for (int n = 0; n < 8; n++) {
#pragma unroll
            for (int m = 0; m < 8; m++) {
                acc[n * 8 + m] =
                    fmaf(qv[n].y, kv[m].y, fmaf(qv[n].x, kv[m].x, acc[n * 8 + m]));
            }
        }
    }

    __shared__ float red[64];
    if (tid < 64) red[tid] = 0.f;
    __syncthreads();
    int ln = tid & 31;
#pragma unroll
    for (int j = 0; j < 64; j++) {
        float v = acc[j];
#pragma unroll
        for (int o = 16; o > 0; o >>= 1) { v += __shfl_down_sync(0xffffffffu, v, o); }
        if (ln == 0) atomicAdd(&red[j], v);
    }
    __syncthreads();
    if (tid < 64) atomicAdd(&g_dots[bi * 64 + tid], red[tid]);
}

/* ---------------- softmax (tiny) ---------------- */
__global__ void softmax_kernel(const float* __restrict__ temp) {
    int t = threadIdx.x;
    if (t >= 32) return;
    int bi = t >> 3, n = t & 7;
    float T  = temp[0];
    float nq = fmaxf(sqrtf(g_sumsq[bi * 16 + n]), 1e-12f);
    float s[8], mx = -1e30f;
#pragma unroll
    for (int m = 0; m < 8; m++) {
        float nk = fmaxf(sqrtf(g_sumsq[bi * 16 + 8 + m]), 1e-12f);
        s[m] = g_dots[bi * 64 + n * 8 + m] / (nq * nk) * T;
        mx = fmaxf(mx, s[m]);
    }
    float sum = 0.f;
#pragma unroll
    for (int m = 0; m < 8; m++) {
        s[m] = expf(s[m] - mx);
        sum += s[m];
    }
    float inv = 1.f / sum;
#pragma unroll
    for (int m = 0; m < 8; m++) { g_attn[bi * 64 + n * 8 + m] = s[m] * inv; }
}

/* ---------------- mix: out[n] = sum_m attn[n][m] * v[m]  (bf16) ---------------- */
__global__ __launch_bounds__(256) void mix_kernel() {
    int bi = blockIdx.y;
    __shared__ float at[64];
    if (threadIdx.x < 64) at[threadIdx.x] = g_attn[bi * 64 + threadIdx.x];
    __syncthreads();
    const __nv_bfloat162* vb =
        (const __nv_bfloat162*)(g_dw + ((size_t)bi * 3 * DIM + 2 * DIM) * HW);
    __nv_bfloat162* ob = (__nv_bfloat162*)(g_mix + (size_t)bi * DIM * HW);
    for (int i = blockIdx.x * 256 + threadIdx.x; i < HL; i += gridDim.x * 256) {
        float2 v[8];
#pragma unroll
        for (int m = 0; m < 8; m++) { v[m] = __bfloat1622float2(vb[(size_t)m * HL + i]); }
#pragma unroll
        for (int n = 0; n < 8; n++) {
            float sx = 0.f, sy = 0.f;
#pragma unroll
            for (int m = 0; m < 8; m++) {
                sx = fmaf(at[n * 8 + m], v[m].x, sx);
                sy = fmaf(at[n * 8 + m], v[m].y, sy);
            }
            ob[(size_t)n * HL + i] = __floats2bfloat162_rn(sx, sy);
        }
    }
}

/* ---------------- launch ---------------- */
extern "C" void kernel_launch(void* const* d_in, const int* in_sizes, int n_in,
                              void* d_out, int out_size) {
    const float* x           = (const float*)d_in[0];
    const float* temperature = (const float*)d_in[1];
    const float* w_qkv       = (const float*)d_in[2];
    const float* b_qkv       = (const float*)d_in[3];
    const float* w_dw        = (const float*)d_in[4];
    const float* b_dw        = (const float*)d_in[5];
    const float* w_proj      = (const float*)d_in[6];
    const float* b_proj      = (const float*)d_in[7];
    float* out = (float*)d_out;

    zero_kernel<<<1, 256>>>();
    convert_x<<<(BATCH * DIM * HW / 4) / 256, 256>>>(x);
    convert_w<<<(3 * DIM * DIM + DIM * DIM) / 256, 256>>>(w_qkv, w_proj);
    gemm_qkv_tc<<<dim3(512, 9), 256>>>(b_qkv);
    dwconv_kernel<<<dim3(1, 8, BATCH * 3 * DIM), 256>>>(w_dw, b_dw);
    dots_kernel<<<dim3(192, BATCH), 256>>>();
    softmax_kernel<<<1, 32>>>(temperature);
    mix_kernel<<<dim3(192, BATCH), 256>>>();
    gemm_proj_tc<<<dim3(512, 3), 256>>>(b_proj, x, out);
}